// round 3
// baseline (speedup 1.0000x reference)
#include <cuda_runtime.h>
#include <math.h>

#define NB 16
#define NT 50
#define NA 3
#define NG 76
#define PLANE (NG*NG)            // 5776
#define NC 85
#define CH (NA*NC)               // 255
#define NBT (NB*NT)              // 800
#define CELL_WORDS ((PLANE + 31) / 32)   // 181
#define TOTAL_CONF (NB*NA*PLANE)         // 277248
#define THREADS 512
#define DENSE_BLOCKS 96                  // 2 per (b,a) plane
#define GRID (DENSE_BLOCKS + 1)
#define HALF (PLANE / 2)                 // 2888 floats per dense block
#define HALF4 (HALF / 4)                 // 722 float4

// ---------------- device scratch (static zero-init; ticket self-resets) ----------
__device__ float g_dense[DENSE_BLOCKS];
__device__ float g_b[8];     // sx, sy, sw, sh, sobj, nm, corr_sum, corr_cnt_mask
__device__ int   g_nz;
__device__ int   g_done;     // reset to 0 by combiner each replay

__device__ __forceinline__ float softplus_f(float v) {
    // ln(1+e^v) == -ln(1 - sigmoid(v) + 1e-12) to fp32 rounding for |v| small
    float a = fabsf(v);
    return fmaxf(v, 0.f) + __logf(1.f + __expf(-a));
}

__device__ __forceinline__ float block_reduce512(float v, float* sh) {
    int lane = threadIdx.x & 31, wid = threadIdx.x >> 5;
    #pragma unroll
    for (int o = 16; o; o >>= 1) v += __shfl_down_sync(0xffffffffu, v, o);
    if (lane == 0) sh[wid] = v;
    __syncthreads();
    if (wid == 0) {
        v = (lane < 16) ? sh[lane] : 0.f;
        #pragma unroll
        for (int o = 8; o; o >>= 1) v += __shfl_down_sync(0xffffffffu, v, o);
    }
    return v;  // valid in thread 0
}

__global__ __launch_bounds__(THREADS, 1)
void k_yolo(const float* __restrict__ sample,
            const float* __restrict__ targets,
            const float* __restrict__ anchors,
            float* __restrict__ out)
{
    __shared__ int      s_key[NBT];
    __shared__ float    s_gx[NBT], s_gy[NBT], s_gw[NBT], s_gh[NBT];
    __shared__ unsigned s_zero[CELL_WORDS];
    __shared__ int      s_zlist[NBT];
    __shared__ int      s_nz;
    __shared__ float    s_acc[16][8];
    __shared__ float    s_red[16];
    __shared__ int      s_last;

    const int tid = threadIdx.x;
    const int blk = blockIdx.x;

    if (blk < DENSE_BLOCKS) {
        // ---------------- dense softplus over half a conf plane ----------------
        int ba = blk >> 1;                  // (b,a) plane
        int b = ba / NA, a = ba % NA;
        const float* conf = sample + ((size_t)(b * CH + a * NC + 4)) * PLANE
                                   + (blk & 1) * HALF;
        const float4* c4 = (const float4*)conf;
        float4 v0 = c4[tid];
        bool h2 = (tid + THREADS) < HALF4;  // 210 threads take a 2nd vec
        float4 v1 = h2 ? c4[tid + THREADS] : make_float4(0.f, 0.f, 0.f, 0.f);
        float s = softplus_f(v0.x) + softplus_f(v0.y) + softplus_f(v0.z) + softplus_f(v0.w);
        if (h2)
            s += softplus_f(v1.x) + softplus_f(v1.y) + softplus_f(v1.z) + softplus_f(v1.w);
        float rs = block_reduce512(s, s_red);
        if (tid == 0) g_dense[blk] = rs;
    } else {
        // ---------------- builder block: targets, sparse losses, corrections ----
        if (tid < CELL_WORDS) s_zero[tid] = 0u;
        if (tid == 0) s_nz = 0;

        const float stride = 608.0f / (float)NG;   // 8
        float awS[NA], ahS[NA];
        #pragma unroll
        for (int a = 0; a < NA; a++) {
            awS[a] = anchors[2*a]   / stride;
            ahS[a] = anchors[2*a+1] / stride;
        }
        __syncthreads();

        for (int t = tid; t < NBT; t += THREADS) {
            int b = t / NT;
            const float* tg = targets + (size_t)t * 5;
            const float* t0 = targets + (size_t)(b*NT) * 5;
            float s5 = tg[0] + tg[1] + tg[2] + tg[3] + tg[4];
            bool mm = s5 > 0.f;
            float gx = (mm ? tg[1] : t0[1]) * NG;
            float gy = (mm ? tg[2] : t0[2]) * NG;
            float gw = (mm ? tg[3] : t0[3]) * NG;
            float gh = (mm ? tg[4] : t0[4]) * NG;
            int gi = (int)gx, gj = (int)gy;

            float best = -1e30f; int bn = 0; bool ign = false;
            #pragma unroll
            for (int a = 0; a < NA; a++) {
                float iw = fminf(gw, awS[a]) + 1.f;
                float ih = fminf(gh, ahS[a]) + 1.f;
                float inter = fmaxf(iw, 0.f) * fmaxf(ih, 0.f);
                float denom = (gw + 1.f) * (gh + 1.f)
                            + (awS[a] + 1.f) * (ahS[a] + 1.f) - inter + 1e-12f;
                float iou = inter / denom;
                if (iou > 0.5f) ign = true;
                if (iou > best) { best = iou; bn = a; }  // first-max wins ties
            }
            int cell = gj * NG + gi;
            if (ign) atomicOr(&s_zero[cell >> 5], 1u << (cell & 31));
            s_key[t] = (b * NA + bn) * PLANE + cell;
            s_gx[t] = gx; s_gy[t] = gy; s_gw[t] = gw; s_gh[t] = gh;
        }
        __syncthreads();

        // compact ignore-cell list
        if (tid < CELL_WORDS) {
            unsigned w = s_zero[tid];
            int n = __popc(w);
            if (n) {
                int pos = atomicAdd(&s_nz, n);
                while (w) {
                    int bit = __ffs(w) - 1; w &= w - 1;
                    s_zlist[pos++] = tid * 32 + bit;
                }
            }
        }
        __syncthreads();
        int nz = s_nz;

        float acc[8];
        #pragma unroll
        for (int c = 0; c < 8; c++) acc[c] = 0.f;

        // winner pass: sparse loss terms + mask correction
        for (int t = tid; t < NBT; t += THREADS) {
            int b = t / NT, ti = t % NT;
            int mykey = s_key[t];
            bool winner = true;
            int base = b * NT;
            for (int t2 = ti + 1; t2 < NT; t2++)
                if (s_key[base + t2] == mykey) { winner = false; break; }
            if (!winner) continue;

            float gx = s_gx[t], gy = s_gy[t], gw = s_gw[t], gh = s_gh[t];
            int cell = mykey % PLANE;
            int bn   = (mykey / PLANE) % NA;
            int gi = (int)gx, gj = (int)gy;
            size_t off = ((size_t)(b * CH + bn * NC)) * PLANE + (size_t)cell;
            float p0 = sample[off];
            float p1 = sample[off + 1 * PLANE];
            float p2 = sample[off + 2 * PLANE];
            float p3 = sample[off + 3 * PLANE];
            float p4 = sample[off + 4 * PLANE];

            float x  = 1.f / (1.f + __expf(-p0));
            float y  = 1.f / (1.f + __expf(-p1));
            float pc = 1.f / (1.f + __expf(-p4));
            float tx = gx - (float)gi;
            float ty = gy - (float)gj;
            float tw = __logf(gw / awS[bn] + 1e-16f);
            float th = __logf(gh / ahS[bn] + 1e-16f);

            float dx = x - tx, dy = y - ty, dw = p2 - tw, dh = p3 - th;
            acc[0] += dx * dx; acc[1] += dy * dy;
            acc[2] += dw * dw; acc[3] += dh * dh;
            acc[4] += -__logf(pc + 1e-12f);
            acc[5] += 1.f;
            // mask position not in an ignore cell -> dense sum still holds it
            if (!((s_zero[cell >> 5] >> (cell & 31)) & 1u)) {
                acc[6] += softplus_f(p4);
                acc[7] += 1.f;
            }
        }

        // ignore-cell corrections: all 48 planes at each ignore cell
        int pairs = 48 * nz;
        for (int i = tid; i < pairs; i += THREADS) {
            int cell = s_zlist[i / 48];
            int p = i % 48;
            int b = p / NA, a = p % NA;
            float v = sample[((size_t)(b * CH + a * NC + 4)) * PLANE + (size_t)cell];
            acc[6] += softplus_f(v);
        }

        // one-barrier 8-way reduction
        {
            int lane = tid & 31, wid = tid >> 5;
            #pragma unroll
            for (int c = 0; c < 8; c++)
                #pragma unroll
                for (int o = 16; o; o >>= 1)
                    acc[c] += __shfl_down_sync(0xffffffffu, acc[c], o);
            if (lane == 0)
                #pragma unroll
                for (int c = 0; c < 8; c++) s_acc[wid][c] = acc[c];
            __syncthreads();
            if (tid < 8) {
                float s = 0.f;
                #pragma unroll
                for (int w = 0; w < 16; w++) s += s_acc[w][tid];
                g_b[tid] = s;
            }
            if (tid == 0) g_nz = nz;
        }
    }

    // ---------------- last-block combine ----------------
    if (tid == 0) {
        __threadfence();
        s_last = (atomicAdd(&g_done, 1) == GRID - 1) ? 1 : 0;
    }
    __syncthreads();
    if (s_last) {
        float v = (tid < DENSE_BLOCKS) ? g_dense[tid] : 0.f;
        float dsum = block_reduce512(v, s_red);
        if (tid == 0) {
            float nm   = fmaxf(g_b[5], 1.f);
            float lx   = 2.0f * g_b[0] / nm;
            float ly   = 2.0f * g_b[1] / nm;
            float lw   = 1.6f * g_b[2] / nm;
            float lh   = 1.6f * g_b[3] / nm;
            float lobj = 1.0f * g_b[4] / nm;
            float ncnt = (float)(TOTAL_CONF - 48 * g_nz) - g_b[7];
            float lnoobj = 0.5f * (dsum - g_b[6]) / fmaxf(ncnt, 1.f);
            out[0] = lx + ly + lw + lh + lnoobj + lobj;
            out[1] = lx; out[2] = ly; out[3] = lw; out[4] = lh;
            out[5] = lobj; out[6] = lnoobj;
            atomicExch(&g_done, 0);   // graph-replay safe reset
        }
    }
}

extern "C" void kernel_launch(void* const* d_in, const int* in_sizes, int n_in,
                              void* d_out, int out_size)
{
    const float* sample  = (const float*)d_in[0];
    const float* targets = (const float*)d_in[1];
    const float* anchors = (const float*)d_in[2];
    float* out = (float*)d_out;

    k_yolo<<<GRID, THREADS>>>(sample, targets, anchors, out);
}

// round 4
// speedup vs baseline: 1.3170x; 1.3170x over previous
#include <cuda_runtime.h>
#include <math.h>

#define NB 16
#define NT 50
#define NA 3
#define NG 76
#define PLANE (NG*NG)            // 5776
#define NC 85
#define CH (NA*NC)               // 255
#define NBT (NB*NT)              // 800
#define CELL_WORDS ((PLANE + 31) / 32)   // 181
#define TOTAL_CONF (NB*NA*PLANE)         // 277248
#define THREADS 1024
#define DENSE_BLOCKS 48                  // one per (b,a) conf plane
#define GRID (DENSE_BLOCKS + 1)
#define PLANE4 (PLANE / 4)               // 1444 float4 per plane

// ---------------- device scratch (ticket self-resets each replay) ----------
__device__ float g_dense[DENSE_BLOCKS];
__device__ float g_b[8];     // sx, sy, sw, sh, sobj, nm, corr_sum, corr_cnt
__device__ int   g_nz;
__device__ int   g_done;

__device__ __forceinline__ float softplus_f(float v) {
    // ln(1+e^v) == -ln(1 - sigmoid(v) + 1e-12) to fp32 rounding here
    float a = fabsf(v);
    return fmaxf(v, 0.f) + __logf(1.f + __expf(-a));
}

__device__ __forceinline__ float block_reduce1024(float v, float* sh) {
    int lane = threadIdx.x & 31, wid = threadIdx.x >> 5;
    #pragma unroll
    for (int o = 16; o; o >>= 1) v += __shfl_down_sync(0xffffffffu, v, o);
    if (lane == 0) sh[wid] = v;
    __syncthreads();
    if (wid == 0) {
        v = sh[lane];   // 32 warps exactly
        #pragma unroll
        for (int o = 16; o; o >>= 1) v += __shfl_down_sync(0xffffffffu, v, o);
    }
    return v;  // valid in thread 0
}

__global__ __launch_bounds__(THREADS, 1)
void k_yolo(const float* __restrict__ sample,
            const float* __restrict__ targets,
            const float* __restrict__ anchors,
            float* __restrict__ out)
{
    __shared__ int      s_key[NBT];
    __shared__ float    s_gx[NBT], s_gy[NBT], s_gw[NBT], s_gh[NBT];
    __shared__ unsigned s_zero[CELL_WORDS];
    __shared__ int      s_zlist[NBT];
    __shared__ int      s_nz;
    __shared__ float    s_acc[32][8];
    __shared__ float    s_red[32];
    __shared__ int      s_last;

    const int tid = threadIdx.x;
    const int blk = blockIdx.x;

    if (blk < DENSE_BLOCKS) {
        // ---------------- dense softplus over one conf plane ----------------
        int b = blk / NA, a = blk % NA;
        const float4* c4 = (const float4*)(sample + ((size_t)(b * CH + a * NC + 4)) * PLANE);
        // issue both vector loads up front -> single memory round
        float4 v0 = c4[tid];                          // tid < 1024 < 1444 always valid
        bool h2 = (tid + THREADS) < PLANE4;           // 420 threads take a 2nd vec
        float4 v1 = h2 ? c4[tid + THREADS] : make_float4(0.f, 0.f, 0.f, 0.f);
        float s = softplus_f(v0.x) + softplus_f(v0.y) + softplus_f(v0.z) + softplus_f(v0.w);
        if (h2)
            s += softplus_f(v1.x) + softplus_f(v1.y) + softplus_f(v1.z) + softplus_f(v1.w);
        float rs = block_reduce1024(s, s_red);
        if (tid == 0) g_dense[blk] = rs;
    } else {
        // ---------------- builder block ----------------
        if (tid < CELL_WORDS) s_zero[tid] = 0u;
        if (tid == 0) s_nz = 0;

        const float stride = 608.0f / (float)NG;   // 8
        float awS[NA], ahS[NA];
        #pragma unroll
        for (int a = 0; a < NA; a++) {
            awS[a] = anchors[2*a]   / stride;
            ahS[a] = anchors[2*a+1] / stride;
        }
        __syncthreads();

        if (tid < NBT) {
            int b = tid / NT;
            const float* tg = targets + (size_t)tid * 5;
            const float* t0 = targets + (size_t)(b*NT) * 5;
            float s5 = tg[0] + tg[1] + tg[2] + tg[3] + tg[4];
            bool mm = s5 > 0.f;
            float gx = (mm ? tg[1] : t0[1]) * NG;
            float gy = (mm ? tg[2] : t0[2]) * NG;
            float gw = (mm ? tg[3] : t0[3]) * NG;
            float gh = (mm ? tg[4] : t0[4]) * NG;
            int gi = (int)gx, gj = (int)gy;

            float best = -1e30f; int bn = 0; bool ign = false;
            #pragma unroll
            for (int a = 0; a < NA; a++) {
                float iw = fminf(gw, awS[a]) + 1.f;
                float ih = fminf(gh, ahS[a]) + 1.f;
                float inter = fmaxf(iw, 0.f) * fmaxf(ih, 0.f);
                float denom = (gw + 1.f) * (gh + 1.f)
                            + (awS[a] + 1.f) * (ahS[a] + 1.f) - inter + 1e-12f;
                float iou = inter / denom;
                ign |= (iou > 0.5f);
                if (iou > best) { best = iou; bn = a; }  // first-max wins ties
            }
            int cell = gj * NG + gi;
            if (ign) atomicOr(&s_zero[cell >> 5], 1u << (cell & 31));
            s_key[tid] = (b * NA + bn) * PLANE + cell;
            s_gx[tid] = gx; s_gy[tid] = gy; s_gw[tid] = gw; s_gh[tid] = gh;
        }
        __syncthreads();

        // compact ignore-cell list
        if (tid < CELL_WORDS) {
            unsigned w = s_zero[tid];
            int n = __popc(w);
            if (n) {
                int pos = atomicAdd(&s_nz, n);
                while (w) {
                    int bit = __ffs(w) - 1; w &= w - 1;
                    s_zlist[pos++] = tid * 32 + bit;
                }
            }
        }
        __syncthreads();
        int nz = s_nz;

        float acc[8];
        #pragma unroll
        for (int c = 0; c < 8; c++) acc[c] = 0.f;

        if (tid < NBT) {
            int b = tid / NT, ti = tid % NT;
            int base = b * NT;
            int mykey = s_key[tid];
            // branchless, fully-unrolled last-wins scan: 50 independent LDS
            bool winner = true;
            #pragma unroll
            for (int t2 = 0; t2 < NT; t2++) {
                int k2 = s_key[base + t2];
                winner &= !((t2 > ti) & (k2 == mykey));
            }

            if (winner) {
                float gx = s_gx[tid], gy = s_gy[tid], gw = s_gw[tid], gh = s_gh[tid];
                int cell = mykey % PLANE;
                int bn   = (mykey / PLANE) % NA;
                int gi = (int)gx, gj = (int)gy;
                size_t off = ((size_t)(b * CH + bn * NC)) * PLANE + (size_t)cell;
                float p0 = sample[off];
                float p1 = sample[off + 1 * PLANE];
                float p2 = sample[off + 2 * PLANE];
                float p3 = sample[off + 3 * PLANE];
                float p4 = sample[off + 4 * PLANE];

                float x  = 1.f / (1.f + __expf(-p0));
                float y  = 1.f / (1.f + __expf(-p1));
                float pc = 1.f / (1.f + __expf(-p4));
                float tx = gx - (float)gi;
                float ty = gy - (float)gj;
                float tw = __logf(gw / awS[bn] + 1e-16f);
                float th = __logf(gh / ahS[bn] + 1e-16f);

                float dx = x - tx, dy = y - ty, dw = p2 - tw, dh = p3 - th;
                acc[0] = dx * dx; acc[1] = dy * dy;
                acc[2] = dw * dw; acc[3] = dh * dh;
                acc[4] = -__logf(pc + 1e-12f);
                acc[5] = 1.f;
                // mask position not in an ignore cell -> dense sum holds it
                if (!((s_zero[cell >> 5] >> (cell & 31)) & 1u)) {
                    acc[6] = softplus_f(p4);
                    acc[7] = 1.f;
                }
            }
        }

        // ignore-cell corrections: all 48 planes at each ignore cell
        int pairs = 48 * nz;
        for (int i = tid; i < pairs; i += THREADS) {
            int cell = s_zlist[i / 48];
            int p = i % 48;
            int b = p / NA, a = p % NA;
            float v = sample[((size_t)(b * CH + a * NC + 4)) * PLANE + (size_t)cell];
            acc[6] += softplus_f(v);
        }

        // one-barrier 8-way reduction (32 warps)
        {
            int lane = tid & 31, wid = tid >> 5;
            #pragma unroll
            for (int c = 0; c < 8; c++)
                #pragma unroll
                for (int o = 16; o; o >>= 1)
                    acc[c] += __shfl_down_sync(0xffffffffu, acc[c], o);
            if (lane == 0)
                #pragma unroll
                for (int c = 0; c < 8; c++) s_acc[wid][c] = acc[c];
            __syncthreads();
            if (tid < 8) {
                float s = 0.f;
                #pragma unroll
                for (int w = 0; w < 32; w++) s += s_acc[w][tid];
                g_b[tid] = s;
            }
            if (tid == 0) g_nz = nz;
        }
    }

    // ---------------- last-block combine ----------------
    if (tid == 0) {
        __threadfence();
        s_last = (atomicAdd(&g_done, 1) == GRID - 1) ? 1 : 0;
    }
    __syncthreads();
    if (s_last) {
        float v = (tid < DENSE_BLOCKS) ? g_dense[tid] : 0.f;
        float dsum = block_reduce1024(v, s_red);
        if (tid == 0) {
            float nm   = fmaxf(g_b[5], 1.f);
            float lx   = 2.0f * g_b[0] / nm;
            float ly   = 2.0f * g_b[1] / nm;
            float lw   = 1.6f * g_b[2] / nm;
            float lh   = 1.6f * g_b[3] / nm;
            float lobj = 1.0f * g_b[4] / nm;
            float ncnt = (float)(TOTAL_CONF - 48 * g_nz) - g_b[7];
            float lnoobj = 0.5f * (dsum - g_b[6]) / fmaxf(ncnt, 1.f);
            out[0] = lx + ly + lw + lh + lnoobj + lobj;
            out[1] = lx; out[2] = ly; out[3] = lw; out[4] = lh;
            out[5] = lobj; out[6] = lnoobj;
            atomicExch(&g_done, 0);   // graph-replay safe reset
        }
    }
}

extern "C" void kernel_launch(void* const* d_in, const int* in_sizes, int n_in,
                              void* d_out, int out_size)
{
    const float* sample  = (const float*)d_in[0];
    const float* targets = (const float*)d_in[1];
    const float* anchors = (const float*)d_in[2];
    float* out = (float*)d_out;

    k_yolo<<<GRID, THREADS>>>(sample, targets, anchors, out);
}

// round 5
// speedup vs baseline: 1.3400x; 1.0175x over previous
#include <cuda_runtime.h>
#include <math.h>

#define NB 16
#define NT 50
#define NA 3
#define NG 76
#define PLANE (NG*NG)            // 5776
#define NC 85
#define CH (NA*NC)               // 255
#define NBT (NB*NT)              // 800
#define CELL_WORDS ((PLANE + 31) / 32)   // 181
#define TOTAL_CONF (NB*NA*PLANE)         // 277248
#define THREADS 1024
#define DENSE_BLOCKS 144
#define GRID (DENSE_BLOCKS + 1)
#define PLANE4 (PLANE / 4)               // 1444 float4 per plane
#define TOTAL4 (48 * PLANE4)             // 69312 float4
#define BASE_CHUNK (TOTAL4 / DENSE_BLOCKS)       // 481
#define EXTRA (TOTAL4 - BASE_CHUNK * DENSE_BLOCKS) // 48 blocks get +1

// ---------------- device scratch (ticket self-resets each replay) ----------
__device__ float g_dense[DENSE_BLOCKS];
__device__ float g_b[8];     // sx, sy, sw, sh, sobj, nm, corr_sum, corr_cnt
__device__ int   g_nz;
__device__ int   g_done;

__device__ __forceinline__ float softplus_f(float v) {
    float a = fabsf(v);
    return fmaxf(v, 0.f) + __logf(1.f + __expf(-a));
}

__device__ __forceinline__ float block_reduce1024(float v, float* sh) {
    int lane = threadIdx.x & 31, wid = threadIdx.x >> 5;
    #pragma unroll
    for (int o = 16; o; o >>= 1) v += __shfl_down_sync(0xffffffffu, v, o);
    if (lane == 0) sh[wid] = v;
    __syncthreads();
    if (wid == 0) {
        v = sh[lane];   // exactly 32 warps
        #pragma unroll
        for (int o = 16; o; o >>= 1) v += __shfl_down_sync(0xffffffffu, v, o);
    }
    return v;  // valid in thread 0
}

__global__ __launch_bounds__(THREADS, 1)
void k_yolo(const float* __restrict__ sample,
            const float* __restrict__ targets,
            const float* __restrict__ anchors,
            float* __restrict__ out)
{
    __shared__ int      s_key[NBT];
    __shared__ float    s_gx[NBT], s_gy[NBT], s_gw[NBT], s_gh[NBT];
    __shared__ unsigned s_zero[CELL_WORDS];
    __shared__ int      s_zlist[NBT];
    __shared__ int      s_nz;
    __shared__ float    s_acc[32][8];
    __shared__ float    s_red[32];
    __shared__ int      s_last;

    const int tid = threadIdx.x;
    const int blk = blockIdx.x;

    if (blk < DENSE_BLOCKS) {
        // ------------- dense softplus, ~482 float4 per block -------------
        int start = blk * BASE_CHUNK + min(blk, EXTRA);
        int cnt   = BASE_CHUNK + (blk < EXTRA ? 1 : 0);
        float s = 0.f;
        if (tid < cnt) {
            int gi4 = start + tid;                 // global float4 index
            int plane = gi4 / PLANE4;              // which (b,a) conf plane
            int off   = gi4 - plane * PLANE4;
            // channel index: b*CH + a*NC + 4 == 85*plane + 4
            const float4* c4 = (const float4*)sample + (size_t)(85 * plane + 4) * PLANE4 + off;
            float4 v = *c4;
            // softplus sum via log-of-product: 4 exp + 1 log (vs 4+4)
            float srelu = fmaxf(v.x, 0.f) + fmaxf(v.y, 0.f)
                        + fmaxf(v.z, 0.f) + fmaxf(v.w, 0.f);
            float p = (1.f + __expf(-fabsf(v.x)))
                    * (1.f + __expf(-fabsf(v.y)))
                    * (1.f + __expf(-fabsf(v.z)))
                    * (1.f + __expf(-fabsf(v.w)));
            s = srelu + __logf(p);
        }
        float rs = block_reduce1024(s, s_red);
        if (tid == 0) g_dense[blk] = rs;
    } else {
        // ---------------- builder block ----------------
        if (tid < CELL_WORDS) s_zero[tid] = 0u;
        if (tid == 0) s_nz = 0;

        const float stride = 608.0f / (float)NG;   // 8
        float awS[NA], ahS[NA];
        #pragma unroll
        for (int a = 0; a < NA; a++) {
            awS[a] = anchors[2*a]   / stride;
            ahS[a] = anchors[2*a+1] / stride;
        }
        __syncthreads();

        if (tid < NBT) {
            int b = tid / NT;
            const float* tg = targets + (size_t)tid * 5;
            const float* t0 = targets + (size_t)(b*NT) * 5;
            float s5 = tg[0] + tg[1] + tg[2] + tg[3] + tg[4];
            bool mm = s5 > 0.f;
            float gx = (mm ? tg[1] : t0[1]) * NG;
            float gy = (mm ? tg[2] : t0[2]) * NG;
            float gw = (mm ? tg[3] : t0[3]) * NG;
            float gh = (mm ? tg[4] : t0[4]) * NG;
            int gi = (int)gx, gj = (int)gy;

            float best = -1e30f; int bn = 0; bool ign = false;
            #pragma unroll
            for (int a = 0; a < NA; a++) {
                float iw = fminf(gw, awS[a]) + 1.f;
                float ih = fminf(gh, ahS[a]) + 1.f;
                float inter = fmaxf(iw, 0.f) * fmaxf(ih, 0.f);
                float denom = (gw + 1.f) * (gh + 1.f)
                            + (awS[a] + 1.f) * (ahS[a] + 1.f) - inter + 1e-12f;
                float iou = inter / denom;
                ign |= (iou > 0.5f);
                if (iou > best) { best = iou; bn = a; }  // first-max wins ties
            }
            int cell = gj * NG + gi;
            if (ign) atomicOr(&s_zero[cell >> 5], 1u << (cell & 31));
            s_key[tid] = (b * NA + bn) * PLANE + cell;
            s_gx[tid] = gx; s_gy[tid] = gy; s_gw[tid] = gw; s_gh[tid] = gh;
        }
        __syncthreads();

        // compact ignore-cell list
        if (tid < CELL_WORDS) {
            unsigned w = s_zero[tid];
            int n = __popc(w);
            if (n) {
                int pos = atomicAdd(&s_nz, n);
                while (w) {
                    int bit = __ffs(w) - 1; w &= w - 1;
                    s_zlist[pos++] = tid * 32 + bit;
                }
            }
        }
        __syncthreads();
        int nz = s_nz;

        float acc[8];
        #pragma unroll
        for (int c = 0; c < 8; c++) acc[c] = 0.f;

        if (tid < NBT) {
            int b = tid / NT, ti = tid % NT;
            int base = b * NT;
            int mykey = s_key[tid];
            // branchless, fully-unrolled last-wins scan: 50 independent LDS
            bool winner = true;
            #pragma unroll
            for (int t2 = 0; t2 < NT; t2++) {
                int k2 = s_key[base + t2];
                winner &= !((t2 > ti) & (k2 == mykey));
            }

            if (winner) {
                float gx = s_gx[tid], gy = s_gy[tid], gw = s_gw[tid], gh = s_gh[tid];
                int cell = mykey % PLANE;
                int bn   = (mykey / PLANE) % NA;
                int gi = (int)gx, gj = (int)gy;
                size_t off = ((size_t)(b * CH + bn * NC)) * PLANE + (size_t)cell;
                float p0 = sample[off];
                float p1 = sample[off + 1 * PLANE];
                float p2 = sample[off + 2 * PLANE];
                float p3 = sample[off + 3 * PLANE];
                float p4 = sample[off + 4 * PLANE];

                float x  = 1.f / (1.f + __expf(-p0));
                float y  = 1.f / (1.f + __expf(-p1));
                float pc = 1.f / (1.f + __expf(-p4));
                float tx = gx - (float)gi;
                float ty = gy - (float)gj;
                float tw = __logf(gw / awS[bn] + 1e-16f);
                float th = __logf(gh / ahS[bn] + 1e-16f);

                float dx = x - tx, dy = y - ty, dw = p2 - tw, dh = p3 - th;
                acc[0] = dx * dx; acc[1] = dy * dy;
                acc[2] = dw * dw; acc[3] = dh * dh;
                acc[4] = -__logf(pc + 1e-12f);
                acc[5] = 1.f;
                // mask position not in an ignore cell -> dense sum holds it
                if (!((s_zero[cell >> 5] >> (cell & 31)) & 1u)) {
                    acc[6] = softplus_f(p4);
                    acc[7] = 1.f;
                }
            }
        }

        // ignore-cell corrections: all 48 planes at each ignore cell
        int pairs = 48 * nz;
        for (int i = tid; i < pairs; i += THREADS) {
            int cell = s_zlist[i / 48];
            int p = i % 48;
            int b = p / NA, a = p % NA;
            float v = sample[((size_t)(b * CH + a * NC + 4)) * PLANE + (size_t)cell];
            acc[6] += softplus_f(v);
        }

        // one-barrier 8-way reduction (32 warps)
        {
            int lane = tid & 31, wid = tid >> 5;
            #pragma unroll
            for (int c = 0; c < 8; c++)
                #pragma unroll
                for (int o = 16; o; o >>= 1)
                    acc[c] += __shfl_down_sync(0xffffffffu, acc[c], o);
            if (lane == 0)
                #pragma unroll
                for (int c = 0; c < 8; c++) s_acc[wid][c] = acc[c];
            __syncthreads();
            if (tid < 8) {
                float s = 0.f;
                #pragma unroll
                for (int w = 0; w < 32; w++) s += s_acc[w][tid];
                g_b[tid] = s;
            }
            if (tid == 0) g_nz = nz;
        }
    }

    // ---------------- last-block combine ----------------
    if (tid == 0) {
        __threadfence();
        s_last = (atomicAdd(&g_done, 1) == GRID - 1) ? 1 : 0;
    }
    __syncthreads();
    if (s_last) {
        float v = (tid < DENSE_BLOCKS) ? g_dense[tid] : 0.f;
        float dsum = block_reduce1024(v, s_red);
        if (tid == 0) {
            float nm   = fmaxf(g_b[5], 1.f);
            float lx   = 2.0f * g_b[0] / nm;
            float ly   = 2.0f * g_b[1] / nm;
            float lw   = 1.6f * g_b[2] / nm;
            float lh   = 1.6f * g_b[3] / nm;
            float lobj = 1.0f * g_b[4] / nm;
            float ncnt = (float)(TOTAL_CONF - 48 * g_nz) - g_b[7];
            float lnoobj = 0.5f * (dsum - g_b[6]) / fmaxf(ncnt, 1.f);
            out[0] = lx + ly + lw + lh + lnoobj + lobj;
            out[1] = lx; out[2] = ly; out[3] = lw; out[4] = lh;
            out[5] = lobj; out[6] = lnoobj;
            atomicExch(&g_done, 0);   // graph-replay safe reset
        }
    }
}

extern "C" void kernel_launch(void* const* d_in, const int* in_sizes, int n_in,
                              void* d_out, int out_size)
{
    const float* sample  = (const float*)d_in[0];
    const float* targets = (const float*)d_in[1];
    const float* anchors = (const float*)d_in[2];
    float* out = (float*)d_out;

    k_yolo<<<GRID, THREADS>>>(sample, targets, anchors, out);
}

// round 6
// speedup vs baseline: 1.5581x; 1.1628x over previous
#include <cuda_runtime.h>
#include <math.h>

#define NB 16
#define NT 50
#define NA 3
#define NG 76
#define PLANE (NG*NG)            // 5776
#define NC 85
#define CH (NA*NC)               // 255
#define NBT (NB*NT)              // 800
#define CELL_WORDS 181           // ceil(5776/32)
#define TOTAL_CONF (NB*NA*PLANE) // 277248
#define THREADS 1024
#define DENSE_BLOCKS 132
#define GRID 148                 // 132 dense + 16 builders, one wave
#define PLANE4 (PLANE/4)         // 1444
#define TOTAL4 (48*PLANE4)       // 69312
#define BASE_CHUNK (TOTAL4/DENSE_BLOCKS)          // 525
#define EXTRA (TOTAL4 - BASE_CHUNK*DENSE_BLOCKS)  // 12

// ---------------- device scratch (combiner resets bitmap+ticket) ----------
__device__ float    g_dense[DENSE_BLOCKS];
__device__ float    g_bb[NB*6];          // per-batch: sx, sy, sw, sh, sobj, nm
__device__ int      g_wcell[NBT];        // winner cell or -1
__device__ float    g_wsp4[NBT];         // winner softplus(p4)
__device__ unsigned g_zero[CELL_WORDS];  // ignore-cell union (zero-init)
__device__ int      g_done;

__device__ __forceinline__ float softplus_f(float v) {
    float a = fabsf(v);
    return fmaxf(v, 0.f) + __logf(1.f + __expf(-a));
}

__device__ __forceinline__ float block_reduce1024(float v, float* sh) {
    int lane = threadIdx.x & 31, wid = threadIdx.x >> 5;
    #pragma unroll
    for (int o = 16; o; o >>= 1) v += __shfl_down_sync(0xffffffffu, v, o);
    if (lane == 0) sh[wid] = v;
    __syncthreads();
    if (wid == 0) {
        v = sh[lane];   // exactly 32 warps
        #pragma unroll
        for (int o = 16; o; o >>= 1) v += __shfl_down_sync(0xffffffffu, v, o);
    }
    __syncthreads();    // allow back-to-back reuse of sh
    return v;           // valid in thread 0
}

__global__ __launch_bounds__(THREADS, 1)
void k_yolo(const float* __restrict__ sample,
            const float* __restrict__ targets,
            const float* __restrict__ anchors,
            float* __restrict__ out)
{
    __shared__ int      s_key[NT];
    __shared__ float    s_gx[NT], s_gy[NT], s_gw[NT], s_gh[NT];
    __shared__ float    s_slot[NT][6];
    __shared__ unsigned c_zero[CELL_WORDS];
    __shared__ float    s_red[32];
    __shared__ int      s_last;

    const int tid = threadIdx.x;
    const int blk = blockIdx.x;

    if (blk < DENSE_BLOCKS) {
        // ------------- dense softplus, ~525 float4 per block, 1 round -------------
        int start = blk * BASE_CHUNK + min(blk, EXTRA);
        int cnt   = BASE_CHUNK + (blk < EXTRA ? 1 : 0);
        float s = 0.f;
        if (tid < cnt) {
            int gi4 = start + tid;
            int plane = gi4 / PLANE4;       // (b,a) conf plane: channel 85*plane+4
            int off   = gi4 - plane * PLANE4;
            const float4* c4 = (const float4*)sample + (size_t)(85 * plane + 4) * PLANE4 + off;
            float4 v = *c4;
            float srelu = fmaxf(v.x, 0.f) + fmaxf(v.y, 0.f)
                        + fmaxf(v.z, 0.f) + fmaxf(v.w, 0.f);
            float p = (1.f + __expf(-fabsf(v.x)))
                    * (1.f + __expf(-fabsf(v.y)))
                    * (1.f + __expf(-fabsf(v.z)))
                    * (1.f + __expf(-fabsf(v.w)));
            s = srelu + __logf(p);          // 4 exp + 1 log per float4
        }
        float rs = block_reduce1024(s, s_red);
        if (tid == 0) g_dense[blk] = rs;
    } else {
        // ------------- builder block for batch b: 50 targets -------------
        const int b = blk - DENSE_BLOCKS;
        const float stride = 608.0f / (float)NG;   // 8
        float awS[NA], ahS[NA];
        #pragma unroll
        for (int a = 0; a < NA; a++) {
            awS[a] = anchors[2*a]   / stride;
            ahS[a] = anchors[2*a+1] / stride;
        }

        if (tid < NT) {
            const float* tg = targets + (size_t)(b*NT + tid) * 5;
            const float* t0 = targets + (size_t)(b*NT) * 5;
            float s5 = tg[0] + tg[1] + tg[2] + tg[3] + tg[4];
            bool mm = s5 > 0.f;
            float gx = (mm ? tg[1] : t0[1]) * NG;
            float gy = (mm ? tg[2] : t0[2]) * NG;
            float gw = (mm ? tg[3] : t0[3]) * NG;
            float gh = (mm ? tg[4] : t0[4]) * NG;
            int gi = (int)gx, gj = (int)gy;

            float best = -1e30f; int bn = 0; bool ign = false;
            #pragma unroll
            for (int a = 0; a < NA; a++) {
                float iw = fminf(gw, awS[a]) + 1.f;
                float ih = fminf(gh, ahS[a]) + 1.f;
                float inter = fmaxf(iw, 0.f) * fmaxf(ih, 0.f);
                float denom = (gw + 1.f) * (gh + 1.f)
                            + (awS[a] + 1.f) * (ahS[a] + 1.f) - inter + 1e-12f;
                float iou = __fdividef(inter, denom);
                ign |= (iou > 0.5f);
                if (iou > best) { best = iou; bn = a; }  // first-max wins ties
            }
            int cell = gj * NG + gi;
            if (ign) atomicOr(&g_zero[cell >> 5], 1u << (cell & 31));
            s_key[tid] = bn * PLANE + cell;              // within-batch key
            s_gx[tid] = gx; s_gy[tid] = gy; s_gw[tid] = gw; s_gh[tid] = gh;
        }
        __syncthreads();

        if (tid < NT) {
            int mykey = s_key[tid];
            bool winner = true;                          // last-wins scan
            #pragma unroll
            for (int t2 = 0; t2 < NT; t2++)
                winner &= !((t2 > tid) & (s_key[t2] == mykey));

            float a0=0.f,a1=0.f,a2=0.f,a3=0.f,a4=0.f,a5=0.f;
            int wc = -1; float wsp = 0.f;
            if (winner) {
                float gx = s_gx[tid], gy = s_gy[tid], gw = s_gw[tid], gh = s_gh[tid];
                int cell = mykey % PLANE;
                int bn   = mykey / PLANE;
                int gi = (int)gx, gj = (int)gy;
                size_t off = ((size_t)(b * CH + bn * NC)) * PLANE + (size_t)cell;
                float p0 = sample[off];
                float p1 = sample[off + 1 * PLANE];
                float p2 = sample[off + 2 * PLANE];
                float p3 = sample[off + 3 * PLANE];
                float p4 = sample[off + 4 * PLANE];

                float x  = __fdividef(1.f, 1.f + __expf(-p0));
                float y  = __fdividef(1.f, 1.f + __expf(-p1));
                float pc = __fdividef(1.f, 1.f + __expf(-p4));
                float tx = gx - (float)gi;
                float ty = gy - (float)gj;
                float tw = __logf(__fdividef(gw, awS[bn]) + 1e-16f);
                float th = __logf(__fdividef(gh, ahS[bn]) + 1e-16f);

                float dx = x - tx, dy = y - ty, dw = p2 - tw, dh = p3 - th;
                a0 = dx*dx; a1 = dy*dy; a2 = dw*dw; a3 = dh*dh;
                a4 = -__logf(pc + 1e-12f);
                a5 = 1.f;
                wc = cell; wsp = softplus_f(p4);
            }
            s_slot[tid][0]=a0; s_slot[tid][1]=a1; s_slot[tid][2]=a2;
            s_slot[tid][3]=a3; s_slot[tid][4]=a4; s_slot[tid][5]=a5;
            g_wcell[b*NT + tid] = wc;
            g_wsp4[b*NT + tid]  = wsp;
        }
        __syncthreads();
        if (tid < 6) {
            float s = 0.f;
            #pragma unroll
            for (int t = 0; t < NT; t++) s += s_slot[t][tid];
            g_bb[b*6 + tid] = s;                          // deterministic slot
        }
    }

    // ---------------- last-block combine (any block can win the ticket) ----------
    if (tid == 0) {
        __threadfence();
        s_last = (atomicAdd(&g_done, 1) == GRID - 1) ? 1 : 0;
    }
    __syncthreads();
    if (s_last) {
        // snapshot the union bitmap into shared, then reset it for next replay
        float nzp = 0.f;
        if (tid < CELL_WORDS) {
            unsigned w = g_zero[tid];
            c_zero[tid] = w;
            nzp = (float)__popc(w);
        }
        __syncthreads();
        if (tid < CELL_WORDS) g_zero[tid] = 0u;

        float dv = (tid < DENSE_BLOCKS) ? g_dense[tid] : 0.f;
        float dsum = block_reduce1024(dv, s_red);
        float nzf  = block_reduce1024(nzp, s_red);

        // ignore-cell corrections: for every set cell, all 48 conf planes
        float corr = 0.f;
        for (int i = tid; i < CELL_WORDS * 48; i += THREADS) {
            int wi = i / 48, p = i % 48;
            unsigned w = c_zero[wi];
            while (w) {
                int bit = __ffs(w) - 1; w &= w - 1;
                int cell = wi * 32 + bit;
                float v = sample[(size_t)(85 * p + 4) * PLANE + (size_t)cell];
                corr += softplus_f(v);
            }
        }
        // mask-position corrections: winners not inside an ignore cell
        float mcs = 0.f, mcc = 0.f;
        if (tid < NBT) {
            int cell = g_wcell[tid];
            if (cell >= 0 && !((c_zero[cell >> 5] >> (cell & 31)) & 1u)) {
                mcs = g_wsp4[tid];
                mcc = 1.f;
            }
        }
        corr = block_reduce1024(corr, s_red);
        mcs  = block_reduce1024(mcs,  s_red);
        mcc  = block_reduce1024(mcc,  s_red);

        if (tid == 0) {
            float bsum[6];
            #pragma unroll
            for (int f = 0; f < 6; f++) {
                float s = 0.f;
                #pragma unroll
                for (int bb = 0; bb < NB; bb++) s += g_bb[bb*6 + f];
                bsum[f] = s;
            }
            float nm   = fmaxf(bsum[5], 1.f);
            float lx   = 2.0f * bsum[0] / nm;
            float ly   = 2.0f * bsum[1] / nm;
            float lw   = 1.6f * bsum[2] / nm;
            float lh   = 1.6f * bsum[3] / nm;
            float lobj = 1.0f * bsum[4] / nm;
            float ncnt = (float)TOTAL_CONF - 48.f * nzf - mcc;
            float lnoobj = 0.5f * (dsum - corr - mcs) / fmaxf(ncnt, 1.f);
            out[0] = lx + ly + lw + lh + lnoobj + lobj;
            out[1] = lx; out[2] = ly; out[3] = lw; out[4] = lh;
            out[5] = lobj; out[6] = lnoobj;
            atomicExch(&g_done, 0);   // graph-replay safe reset
        }
    }
}

extern "C" void kernel_launch(void* const* d_in, const int* in_sizes, int n_in,
                              void* d_out, int out_size)
{
    const float* sample  = (const float*)d_in[0];
    const float* targets = (const float*)d_in[1];
    const float* anchors = (const float*)d_in[2];
    float* out = (float*)d_out;

    k_yolo<<<GRID, THREADS>>>(sample, targets, anchors, out);
}